// round 3
// baseline (speedup 1.0000x reference)
#include <cuda_runtime.h>
#include <math.h>

// ---------------------------------------------------------------------------
// MetaQDA via conditioned Woodbury / matrix-determinant-lemma restructuring.
//   S_c = L L^T + V_c^T V_c,   V_c = [x_i - xbar (32 rows); sqrt(kappa*N/kN)(xbar - m)]
//   (exact NIW identity: Sum xx^T + kappa mm^T - kN mu mu^T
//        = Sum (x-xbar)(x-xbar)^T + (kappa*N/kN)(xbar-m)(xbar-m)^T)
//   S^{-1} = L^{-T}(I - T^T M^{-1} T)L^{-1},  T = V L^{-T} (33 x D),  M = I + T T^T (SPD!)
//   logdet S = 2 sum log|L_ii| + logdet M   (M SPD, lambda_min = 1 -> well conditioned)
// ---------------------------------------------------------------------------

#define Dd   1024
#define Cc   32
#define SHOTSn 32
#define NSUP 1024
#define Qq   1024
#define KW   34     // rows of T-hat per class: 32 centered + scaled-diff + mu(aux)
#define KV   33     // rows entering the Woodbury capacitance M

// ------------------------- scratch (device globals) -------------------------
__device__ float g_L[Dd * Dd];
__device__ float g_Linv[Dd * Dd];
__device__ float g_Tmp[512 * 512];
__device__ float g_W[Cc * KW * Dd];
__device__ float g_T[Cc * KW * Dd];
__device__ float g_G[Qq * Dd];
__device__ float g_U[Cc * Qq * KW];
__device__ float g_TtT[Cc * KW * KW];
__device__ float g_Kinv[Cc * KW * KW];   // packed KV x KV per class
__device__ float g_b[Cc * KW];
__device__ float g_mu[Cc * Dd];
__device__ float g_xbar[Cc * Dd];
__device__ float g_Gn2[Qq];
__device__ float g_qn2[Qq];
__device__ float g_mun2[Cc];
__device__ float g_qm[Qq * Cc];
__device__ int   g_sample_of[Cc * SHOTSn];

struct Cls {
    float Nj, kN, common_, scale;
    float bias, coefD, inv_common, invscale_half, hh;
};
__device__ Cls   g_cls[Cc];
__device__ float g_kappa_;
__device__ float g_sumlogL;

// ------------------------------- setup --------------------------------------
__global__ void setup_kernel(const int* __restrict__ labels,
                             const float* __restrict__ kappa_p,
                             const float* __restrict__ nu_p,
                             const float* __restrict__ triu_diag) {
    __shared__ int   sl[NSUP];
    __shared__ float red[32];
    int t = threadIdx.x;  // 1024 threads
    sl[t] = labels[t];
    g_sample_of[t] = 0;
    __syncthreads();

    // deterministic within-class position (stable gather)
    int l = sl[t];
    int cnt = 0;
    for (int j = 0; j < t; j++) cnt += (sl[j] == l);
    if (l >= 0 && l < Cc && cnt < SHOTSn) g_sample_of[l * SHOTSn + cnt] = t;

    // sum of log |diag(L)|
    float v = logf(fabsf(triu_diag[t]));
    for (int o = 16; o > 0; o >>= 1) v += __shfl_down_sync(0xffffffffu, v, o);
    if ((t & 31) == 0) red[t >> 5] = v;
    __syncthreads();
    if (t < 32) {
        float s = red[t];
        for (int o = 16; o > 0; o >>= 1) s += __shfl_down_sync(0xffffffffu, s, o);
        if (t == 0) g_sumlogL = s;
    }

    if (t < Cc) {
        int nj = 0;
        for (int j = 0; j < NSUP; j++) nj += (sl[j] == t);
        float kappa_ = fabsf(*kappa_p) + 1e-6f;
        float nu_    = fmaxf(*nu_p, (float)(Dd - 1) + 1e-6f);
        float Njf = (float)nj;
        float kN = kappa_ + Njf;
        float common_ = nu_ + Njf + 1.0f - (float)Dd;
        float scale = (kN + 1.0f) / (common_ * kN);
        Cls c;
        c.Nj = Njf; c.kN = kN; c.common_ = common_; c.scale = scale;
        c.bias = 0.f;
        c.coefD = 0.5f * (common_ + (float)Dd);
        c.inv_common = 1.0f / common_;
        c.invscale_half = 0.5f / scale;
        c.hh = 0.f;
        g_cls[t] = c;
        if (t == 0) g_kappa_ = kappa_;
    }
}

// --------------------------- build L (and zero Linv) -------------------------
__global__ void build_L_kernel(const float* __restrict__ tdiag,
                               const float* __restrict__ tlower) {
    int idx = blockIdx.x * blockDim.x + threadIdx.x;
    if (idx >= Dd * Dd) return;
    int i = idx / Dd, j = idx % Dd;
    float v = (i == j) ? fabsf(tdiag[i]) : (i > j ? tlower[idx] : 0.0f);
    g_L[idx] = v;
    g_Linv[idx] = 0.0f;
}

// ------------------ invert 32x32 lower-triangular diagonal blocks ------------
__global__ void inv_diag_kernel() {
    __shared__ float Ls[32][33];
    __shared__ float Xs[32][33];
    int b = blockIdx.x, t = threadIdx.x;  // 32 threads
    int off = b * 32;
    for (int i = 0; i < 32; i++) Ls[i][t] = g_L[(off + i) * Dd + off + t];
    __syncthreads();
    for (int i = 0; i < 32; i++) {
        float s = (i == t) ? 1.0f : 0.0f;
        for (int k = t; k < i; k++) s -= Ls[i][k] * Xs[k][t];
        Xs[i][t] = (i >= t) ? s / Ls[i][i] : 0.0f;
    }
    __syncthreads();
    for (int i = 0; i < 32; i++) g_Linv[(off + i) * Dd + off + t] = Xs[i][t];
}

// ------------------------------ generic SGEMM --------------------------------
// C = alpha * A @ B  (row-major). TRANSB: logical B[k][n] = Bp[n*ldb + k].
template <bool TRANSB>
__global__ void sgemm_kernel(const float* __restrict__ A, long long sA, int lda,
                             const float* __restrict__ B, long long sB, int ldb,
                             float* __restrict__ Cp, long long sC, int ldc,
                             int M, int N, int K, float alpha) {
    __shared__ float As[16][65];  // [k][m]
    __shared__ float Bs[16][65];  // [k][n]
    A  += blockIdx.z * sA;
    B  += blockIdx.z * sB;
    Cp += blockIdx.z * sC;
    int m0 = blockIdx.y * 64, n0 = blockIdx.x * 64;
    int tid = threadIdx.x;  // 256
    int tm = (tid / 16) * 4;
    int tn = (tid % 16) * 4;
    float acc[4][4] = {};
    for (int k0 = 0; k0 < K; k0 += 16) {
#pragma unroll
        for (int i = 0; i < 4; i++) {
            int idx = tid + i * 256;
            int am = idx / 16, ak = idx % 16;
            float v = 0.f;
            if (m0 + am < M && k0 + ak < K) v = A[(long long)(m0 + am) * lda + k0 + ak];
            As[ak][am] = v;
        }
#pragma unroll
        for (int i = 0; i < 4; i++) {
            int idx = tid + i * 256;
            if (!TRANSB) {
                int bk = idx / 64, bn = idx % 64;
                float v = 0.f;
                if (k0 + bk < K && n0 + bn < N) v = B[(long long)(k0 + bk) * ldb + n0 + bn];
                Bs[bk][bn] = v;
            } else {
                int bn = idx / 16, bk = idx % 16;
                float v = 0.f;
                if (k0 + bk < K && n0 + bn < N) v = B[(long long)(n0 + bn) * ldb + k0 + bk];
                Bs[bk][bn] = v;
            }
        }
        __syncthreads();
#pragma unroll
        for (int k = 0; k < 16; k++) {
            float a[4], b[4];
#pragma unroll
            for (int i = 0; i < 4; i++) a[i] = As[k][tm + i];
#pragma unroll
            for (int j = 0; j < 4; j++) b[j] = Bs[k][tn + j];
#pragma unroll
            for (int i = 0; i < 4; i++)
#pragma unroll
                for (int j = 0; j < 4; j++) acc[i][j] += a[i] * b[j];
        }
        __syncthreads();
    }
#pragma unroll
    for (int i = 0; i < 4; i++) {
        int m = m0 + tm + i;
        if (m >= M) continue;
#pragma unroll
        for (int j = 0; j < 4; j++) {
            int n = n0 + tn + j;
            if (n >= N) continue;
            Cp[(long long)m * ldc + n] = alpha * acc[i][j];
        }
    }
}

// ------------------------- per-class means (xbar, mu) ------------------------
__global__ void build_mu_kernel(const float* __restrict__ support,
                                const float* __restrict__ m) {
    int idx = blockIdx.x * blockDim.x + threadIdx.x;  // over C * D
    if (idx >= Cc * Dd) return;
    int c = idx / Dd, d = idx % Dd;
    float s = 0.f;
    for (int j = 0; j < SHOTSn; j++)
        s += support[(long long)g_sample_of[c * SHOTSn + j] * Dd + d];
    float xbar = s / g_cls[c].Nj;
    float mu = (g_kappa_ * m[d] + s) / g_cls[c].kN;
    g_xbar[idx] = xbar;
    g_mu[idx] = mu;
}

// ------------------------------- build W -------------------------------------
// rows 0..31 : x_i - xbar   (centered samples)
// row  32    : sqrt(kappa*N/kN) * (xbar - m)
// row  33    : mu   (auxiliary, only for e = L^{-1}(q - mu) terms)
__global__ void build_W_kernel(const float* __restrict__ support,
                               const float* __restrict__ m) {
    int idx = blockIdx.x * blockDim.x + threadIdx.x;
    if (idx >= Cc * KW * Dd) return;
    int d = idx % Dd;
    int row = idx / Dd;
    int c = row / KW;
    int k = row % KW;
    float v;
    if (k < SHOTSn) {
        v = support[(long long)g_sample_of[c * SHOTSn + k] * Dd + d] - g_xbar[c * Dd + d];
    } else if (k == SHOTSn) {
        Cls cl = g_cls[c];
        float c2 = sqrtf(g_kappa_ * cl.Nj / cl.kN);
        v = c2 * (g_xbar[c * Dd + d] - m[d]);
    } else {
        v = g_mu[c * Dd + d];
    }
    g_W[idx] = v;
}

// ------------------------------- row norms -----------------------------------
__global__ void rownorm_kernel(const float* __restrict__ X, int ld, float* __restrict__ out) {
    int r = blockIdx.x, t = threadIdx.x;  // 256 threads
    const float* row = X + (long long)r * ld;
    float s = 0.f;
    for (int j = t; j < ld; j += blockDim.x) { float v = row[j]; s += v * v; }
    __shared__ float red[8];
    for (int o = 16; o > 0; o >>= 1) s += __shfl_down_sync(0xffffffffu, s, o);
    if ((t & 31) == 0) red[t >> 5] = s;
    __syncthreads();
    if (t < 32) {
        float v = (t < 8) ? red[t] : 0.f;
        for (int o = 4; o > 0; o >>= 1) v += __shfl_down_sync(0xffffffffu, v, o);
        if (t == 0) out[r] = v;
    }
}

// -------- per-class SPD 33x33 inverse (fp64 Gauss-Jordan) + logdet/bias ------
__global__ void small_inv_kernel() {
    int c = blockIdx.x, t = threadIdx.x;  // 64 threads
    __shared__ double Ms[KV][KV + 1];
    __shared__ double Iv[KV][KV + 1];
    __shared__ double s_logdet;
    __shared__ int    s_piv;
    const float* TtT = g_TtT + c * KW * KW;
    for (int i = t; i < KV * KV; i += blockDim.x) {
        int r = i / KV, cc = i % KV;
        Ms[r][cc] = (double)TtT[r * KW + cc] + (r == cc ? 1.0 : 0.0);  // M = I + T T^T
        Iv[r][cc] = (r == cc) ? 1.0 : 0.0;
    }
    if (t < KV) g_b[c * KW + t] = TtT[t * KW + (KW - 1)];  // t_a . t_mu
    if (t == 0) s_logdet = 0.0;
    __syncthreads();
    for (int k = 0; k < KV; k++) {
        if (t == 0) {
            int p = k; double best = fabs(Ms[k][k]);
            for (int r = k + 1; r < KV; r++) {
                double a = fabs(Ms[r][k]);
                if (a > best) { best = a; p = r; }
            }
            s_piv = p;
        }
        __syncthreads();
        int p = s_piv;
        if (p != k && t < KV) {
            double tmp = Ms[k][t]; Ms[k][t] = Ms[p][t]; Ms[p][t] = tmp;
            tmp = Iv[k][t]; Iv[k][t] = Iv[p][t]; Iv[p][t] = tmp;
        }
        __syncthreads();
        double piv = Ms[k][k];
        if (t == 0) s_logdet += log(fabs(piv));
        double pivinv = 1.0 / piv;
        if (t < KV) { Ms[k][t] *= pivinv; Iv[k][t] *= pivinv; }
        __syncthreads();
        if (t < KV && t != k) {
            double f = Ms[t][k];
            for (int j = 0; j < KV; j++) {
                Ms[t][j] -= f * Ms[k][j];
                Iv[t][j] -= f * Iv[k][j];
            }
        }
        __syncthreads();
    }
    for (int i = t; i < KV * KV; i += blockDim.x)
        g_Kinv[c * KW * KW + i] = (float)Iv[i / KV][i % KV];
    if (t == 0) {
        Cls cl = g_cls[c];
        // det(S) = det(LL^T) * det(I + T T^T);  all factors positive (SPD)
        double logdetS = 2.0 * (double)g_sumlogL + s_logdet;
        double logdet_sigma = (double)Dd * log((double)cl.scale) + logdetS;
        double common_ = (double)cl.common_;
        double bias = lgamma(0.5 * (common_ + (double)Dd)) - lgamma(0.5 * common_)
                    - 0.5 * (double)Dd * log(common_) - 0.5 * logdet_sigma;
        g_cls[c].bias = (float)bias;
        g_cls[c].hh = TtT[(KW - 1) * KW + (KW - 1)];  // ||t_mu||^2
    }
}

// --------------------------------- finalize ----------------------------------
__global__ void finalize_kernel(float* __restrict__ out) {
    int c = blockIdx.y;
    int q = blockIdx.x * blockDim.x + threadIdx.x;
    __shared__ float Ks[KV * KV];
    __shared__ float bs[KV];
    __shared__ Cls cl;
    for (int i = threadIdx.x; i < KV * KV; i += blockDim.x) Ks[i] = g_Kinv[c * KW * KW + i];
    if (threadIdx.x < KV) bs[threadIdx.x] = g_b[c * KW + threadIdx.x];
    if (threadIdx.x == 0) cl = g_cls[c];
    __syncthreads();
    if (q >= Qq) return;
    const float* Ur = g_U + ((long long)c * Qq + q) * KW;
    float v[KV];
    float u33 = Ur[KW - 1];  // g . t_mu
#pragma unroll
    for (int i = 0; i < KV; i++) v[i] = Ur[i] - bs[i];  // u_a = t_a.(g - t_mu)
    float s = 0.f;
#pragma unroll 4
    for (int i = 0; i < KV; i++) {
        float acc = 0.f;
#pragma unroll
        for (int j = 0; j < KV; j++) acc += Ks[i * KV + j] * v[j];
        s += v[i] * acc;
    }
    // diff^T S^{-1} diff = ||L^{-1}diff||^2 - u^T M^{-1} u
    float distA = g_Gn2[q] - 2.0f * u33 + cl.hh - s;
    float dist  = cl.invscale_half * distA
                + 0.5f * (g_qn2[q] - 2.0f * g_qm[q * Cc + c] + g_mun2[c]);
    out[(long long)q * Cc + c] = cl.bias - cl.coefD * log1pf(dist * cl.inv_common);
}

// ------------------------------ host launcher --------------------------------
static void sgemm(const float* A, long long sA, int lda,
                  const float* B, long long sB, int ldb,
                  float* Cmat, long long sC, int ldc,
                  int M, int N, int K, float alpha, bool transB, int batch) {
    dim3 grid((N + 63) / 64, (M + 63) / 64, batch);
    if (transB)
        sgemm_kernel<true><<<grid, 256>>>(A, sA, lda, B, sB, ldb, Cmat, sC, ldc, M, N, K, alpha);
    else
        sgemm_kernel<false><<<grid, 256>>>(A, sA, lda, B, sB, ldb, Cmat, sC, ldc, M, N, K, alpha);
}

extern "C" void kernel_launch(void* const* d_in, const int* in_sizes, int n_in,
                              void* d_out, int out_size) {
    const float* support = (const float*)d_in[0];
    const float* query   = (const float*)d_in[1];
    const int*   labels  = (const int*)d_in[2];
    const float* m       = (const float*)d_in[3];
    const float* kappa   = (const float*)d_in[4];
    const float* nu      = (const float*)d_in[5];
    const float* tdiag   = (const float*)d_in[6];
    const float* tlower  = (const float*)d_in[7];
    float* out = (float*)d_out;

    float *pL, *pLinv, *pTmp, *pW, *pT, *pG, *pU, *pTtT, *pMu, *pGn2, *pqn2, *pmun2, *pQm;
    cudaGetSymbolAddress((void**)&pL, g_L);
    cudaGetSymbolAddress((void**)&pLinv, g_Linv);
    cudaGetSymbolAddress((void**)&pTmp, g_Tmp);
    cudaGetSymbolAddress((void**)&pW, g_W);
    cudaGetSymbolAddress((void**)&pT, g_T);
    cudaGetSymbolAddress((void**)&pG, g_G);
    cudaGetSymbolAddress((void**)&pU, g_U);
    cudaGetSymbolAddress((void**)&pTtT, g_TtT);
    cudaGetSymbolAddress((void**)&pMu, g_mu);
    cudaGetSymbolAddress((void**)&pGn2, g_Gn2);
    cudaGetSymbolAddress((void**)&pqn2, g_qn2);
    cudaGetSymbolAddress((void**)&pmun2, g_mun2);
    cudaGetSymbolAddress((void**)&pQm, g_qm);

    // 1) scalars, per-class params, stable sample gather, sum log|diag L|
    setup_kernel<<<1, NSUP>>>(labels, kappa, nu, tdiag);

    // 2) per-class xbar / mu, then W = [X_c - xbar | sqrt(kN')*(xbar-m) | mu_c]
    build_mu_kernel<<<(Cc * Dd + 255) / 256, 256>>>(support, m);
    build_W_kernel<<<(Cc * KW * Dd + 255) / 256, 256>>>(support, m);

    // 3) L and L^{-1} (recursive-doubling blocked triangular inverse)
    build_L_kernel<<<(Dd * Dd + 255) / 256, 256>>>(tdiag, tlower);
    inv_diag_kernel<<<32, 32>>>();
    for (int lev = 1; lev <= 5; lev++) {
        int s = 32 << (lev - 1);
        int pairs = 32 >> lev;
        long long stride = 2LL * s * (Dd + 1);
        sgemm(pL + (long long)s * Dd, stride, Dd,
              pLinv, stride, Dd,
              pTmp, (long long)s * s, s,
              s, s, s, 1.0f, false, pairs);
        sgemm(pLinv + (long long)s * Dd + s, stride, Dd,
              pTmp, (long long)s * s, s,
              pLinv + (long long)s * Dd, stride, Dd,
              s, s, s, -1.0f, false, pairs);
    }

    // 4) T = W @ Linv^T  (rows are L^{-1} w)  [1088 x 1024]
    sgemm(pW, 0, Dd, pLinv, 0, Dd, pT, 0, Dd, Cc * KW, Dd, Dd, 1.0f, true, 1);
    // 5) G = Qx @ Linv^T  [1024 x 1024]
    sgemm(query, 0, Dd, pLinv, 0, Dd, pG, 0, Dd, Qq, Dd, Dd, 1.0f, true, 1);

    // 6) row norms: ||L^{-1}q||^2, ||q||^2, ||mu||^2
    rownorm_kernel<<<Qq, 256>>>(pG, Dd, pGn2);
    rownorm_kernel<<<Qq, 256>>>(query, Dd, pqn2);
    rownorm_kernel<<<Cc, 256>>>(pMu, Dd, pmun2);

    // 7) T^T T per class [34x34]; M = I + [0:33,0:33] inverted in fp64 + logdet/bias
    sgemm(pT, (long long)KW * Dd, Dd, pT, (long long)KW * Dd, Dd,
          pTtT, (long long)KW * KW, KW, KW, KW, Dd, 1.0f, true, Cc);
    small_inv_kernel<<<Cc, 64>>>();

    // 8) U[c][q][k] = t_k . g_q   (batched, A shared across batch)
    sgemm(pG, 0, Dd, pT, (long long)KW * Dd, Dd,
          pU, (long long)Qq * KW, KW, Qq, KW, Dd, 1.0f, true, Cc);

    // 9) q . mu  [Q x C]
    sgemm(query, 0, Dd, pMu, 0, Cc, pQm, 0, Cc, Qq, Cc, Dd, 1.0f, true, 1);

    // 10) fuse quadratic forms + bias + log1p
    finalize_kernel<<<dim3((Qq + 127) / 128, Cc), 128>>>(out);
}

// round 4
// speedup vs baseline: 1.4622x; 1.4622x over previous
#include <cuda_runtime.h>
#include <math.h>

// ---------------------------------------------------------------------------
// MetaQDA via conditioned Woodbury / matrix-determinant-lemma restructuring.
//   S_c = L L^T + V_c^T V_c,   V_c = [x_i - xbar (32 rows); sqrt(kappa*N/kN)(xbar - m)]
//   S^{-1} = L^{-T}(I - T^T M^{-1} T)L^{-1},  T = V L^{-T} (33 x D),  M = I + T T^T (SPD)
//   logdet S = 2 sum log|L_ii| + logdet M
// ---------------------------------------------------------------------------

#define Dd   1024
#define Cc   32
#define SHOTSn 32
#define NSUP 1024
#define Qq   1024
#define KW   34     // rows of T-hat per class: 32 centered + scaled-diff + mu(aux)
#define KV   33     // rows entering the Woodbury capacitance M
#define NU   (Cc * KW)   // 1088

// ------------------------- scratch (device globals) -------------------------
__device__ float g_L[Dd * Dd];
__device__ float g_Linv[Dd * Dd];
__device__ float g_Tmp[512 * 512];
__device__ float g_W[NU * Dd];
__device__ float g_T[NU * Dd];
__device__ float g_G[Qq * Dd];
__device__ float g_U[Qq * NU];          // [q][c*KW + k]
__device__ float g_TtT[Cc * KW * KW];
__device__ float g_Kinv[Cc * KW * KW];  // packed KV x KV per class
__device__ float g_b[Cc * KW];
__device__ float g_mu[Cc * Dd];
__device__ float g_xbar[Cc * Dd];
__device__ float g_Gn2[Qq];
__device__ float g_qn2[Qq];
__device__ float g_mun2[Cc];
__device__ float g_qm[Qq * Cc];
__device__ int   g_sample_of[Cc * SHOTSn];

struct Cls {
    float Nj, kN, common_, scale;
    float bias, coefD, inv_common, invscale_half, hh;
};
__device__ Cls   g_cls[Cc];
__device__ float g_kappa_;
__device__ float g_sumlogL;

// ------------------------------- setup --------------------------------------
__global__ void setup_kernel(const int* __restrict__ labels,
                             const float* __restrict__ kappa_p,
                             const float* __restrict__ nu_p,
                             const float* __restrict__ triu_diag) {
    __shared__ int   sl[NSUP];
    __shared__ float red[32];
    int t = threadIdx.x;  // 1024 threads
    sl[t] = labels[t];
    g_sample_of[t] = 0;
    __syncthreads();

    int l = sl[t];
    int cnt = 0;
    for (int j = 0; j < t; j++) cnt += (sl[j] == l);
    if (l >= 0 && l < Cc && cnt < SHOTSn) g_sample_of[l * SHOTSn + cnt] = t;

    float v = logf(fabsf(triu_diag[t]));
    for (int o = 16; o > 0; o >>= 1) v += __shfl_down_sync(0xffffffffu, v, o);
    if ((t & 31) == 0) red[t >> 5] = v;
    __syncthreads();
    if (t < 32) {
        float s = red[t];
        for (int o = 16; o > 0; o >>= 1) s += __shfl_down_sync(0xffffffffu, s, o);
        if (t == 0) g_sumlogL = s;
    }

    if (t < Cc) {
        int nj = 0;
        for (int j = 0; j < NSUP; j++) nj += (sl[j] == t);
        float kappa_ = fabsf(*kappa_p) + 1e-6f;
        float nu_    = fmaxf(*nu_p, (float)(Dd - 1) + 1e-6f);
        float Njf = (float)nj;
        float kN = kappa_ + Njf;
        float common_ = nu_ + Njf + 1.0f - (float)Dd;
        float scale = (kN + 1.0f) / (common_ * kN);
        Cls c;
        c.Nj = Njf; c.kN = kN; c.common_ = common_; c.scale = scale;
        c.bias = 0.f;
        c.coefD = 0.5f * (common_ + (float)Dd);
        c.inv_common = 1.0f / common_;
        c.invscale_half = 0.5f / scale;
        c.hh = 0.f;
        g_cls[t] = c;
        if (t == 0) g_kappa_ = kappa_;
    }
}

// --------------------------- build L (and zero Linv) -------------------------
__global__ void build_L_kernel(const float* __restrict__ tdiag,
                               const float* __restrict__ tlower) {
    int idx = blockIdx.x * blockDim.x + threadIdx.x;
    if (idx >= Dd * Dd) return;
    int i = idx / Dd, j = idx % Dd;
    float v = (i == j) ? fabsf(tdiag[i]) : (i > j ? tlower[idx] : 0.0f);
    g_L[idx] = v;
    g_Linv[idx] = 0.0f;
}

// ------------------ invert 32x32 lower-triangular diagonal blocks ------------
__global__ void inv_diag_kernel() {
    __shared__ float Ls[32][33];
    __shared__ float Xs[32][33];
    int b = blockIdx.x, t = threadIdx.x;  // 32 threads
    int off = b * 32;
    for (int i = 0; i < 32; i++) Ls[i][t] = g_L[(off + i) * Dd + off + t];
    __syncthreads();
    for (int i = 0; i < 32; i++) {
        float s = (i == t) ? 1.0f : 0.0f;
        for (int k = t; k < i; k++) s -= Ls[i][k] * Xs[k][t];
        Xs[i][t] = (i >= t) ? s / Ls[i][i] : 0.0f;
    }
    __syncthreads();
    for (int i = 0; i < 32; i++) g_Linv[(off + i) * Dd + off + t] = Xs[i][t];
}

// --------------------- small generic SGEMM (64x64x16, 4x4) -------------------
// C = alpha * A @ B  (row-major). TRANSB: logical B[k][n] = Bp[n*ldb + k].
template <bool TRANSB>
__global__ void sgemm_kernel(const float* __restrict__ A, long long sA, int lda,
                             const float* __restrict__ B, long long sB, int ldb,
                             float* __restrict__ Cp, long long sC, int ldc,
                             int M, int N, int K, float alpha) {
    __shared__ float As[16][65];
    __shared__ float Bs[16][65];
    A  += blockIdx.z * sA;
    B  += blockIdx.z * sB;
    Cp += blockIdx.z * sC;
    int m0 = blockIdx.y * 64, n0 = blockIdx.x * 64;
    int tid = threadIdx.x;  // 256
    int tm = (tid / 16) * 4;
    int tn = (tid % 16) * 4;
    float acc[4][4] = {};
    for (int k0 = 0; k0 < K; k0 += 16) {
#pragma unroll
        for (int i = 0; i < 4; i++) {
            int idx = tid + i * 256;
            int am = idx / 16, ak = idx % 16;
            float v = 0.f;
            if (m0 + am < M && k0 + ak < K) v = A[(long long)(m0 + am) * lda + k0 + ak];
            As[ak][am] = v;
        }
#pragma unroll
        for (int i = 0; i < 4; i++) {
            int idx = tid + i * 256;
            if (!TRANSB) {
                int bk = idx / 64, bn = idx % 64;
                float v = 0.f;
                if (k0 + bk < K && n0 + bn < N) v = B[(long long)(k0 + bk) * ldb + n0 + bn];
                Bs[bk][bn] = v;
            } else {
                int bn = idx / 16, bk = idx % 16;
                float v = 0.f;
                if (k0 + bk < K && n0 + bn < N) v = B[(long long)(n0 + bn) * ldb + k0 + bk];
                Bs[bk][bn] = v;
            }
        }
        __syncthreads();
#pragma unroll
        for (int k = 0; k < 16; k++) {
            float a[4], b[4];
#pragma unroll
            for (int i = 0; i < 4; i++) a[i] = As[k][tm + i];
#pragma unroll
            for (int j = 0; j < 4; j++) b[j] = Bs[k][tn + j];
#pragma unroll
            for (int i = 0; i < 4; i++)
#pragma unroll
                for (int j = 0; j < 4; j++) acc[i][j] += a[i] * b[j];
        }
        __syncthreads();
    }
#pragma unroll
    for (int i = 0; i < 4; i++) {
        int m = m0 + tm + i;
        if (m >= M) continue;
#pragma unroll
        for (int j = 0; j < 4; j++) {
            int n = n0 + tn + j;
            if (n >= N) continue;
            Cp[(long long)m * ldc + n] = alpha * acc[i][j];
        }
    }
}

// ------------------- fast SGEMM core (128x128x8, 8x8, dbuf) ------------------
// Requires K % 8 == 0. lda/ldb multiples of 4. Row-major.
template <bool TRANSB>
__device__ __forceinline__ void sgemm128_core(
    const float* __restrict__ A, int lda,
    const float* __restrict__ B, int ldb,
    float* __restrict__ Cp, int ldc,
    int M, int N, int K, float alpha, int m0, int n0) {
    __shared__ float As[2][8][132];
    __shared__ float Bs[2][8][132];
    const int tid = threadIdx.x;              // 256
    const int tx = tid & 15, ty = tid >> 4;
    const int arow = tid >> 1, ak4 = (tid & 1) * 4;   // A (and B if TRANSB) loads
    const int bk = tid >> 5, bn4 = (tid & 31) * 4;    // B loads if !TRANSB
    const int nk = K >> 3;

    float4 ar, br;
    const float4 fz = make_float4(0.f, 0.f, 0.f, 0.f);

    // prefetch tile 0
    ar = (m0 + arow < M) ? *(const float4*)(A + (long long)(m0 + arow) * lda + ak4) : fz;
    if (TRANSB) {
        br = (n0 + arow < N) ? *(const float4*)(B + (long long)(n0 + arow) * ldb + ak4) : fz;
    } else {
        if (n0 + bn4 + 3 < N) {
            br = *(const float4*)(B + (long long)bk * ldb + n0 + bn4);
        } else {
            const float* Bp = B + (long long)bk * ldb;
            br.x = (n0 + bn4 + 0 < N) ? Bp[n0 + bn4 + 0] : 0.f;
            br.y = (n0 + bn4 + 1 < N) ? Bp[n0 + bn4 + 1] : 0.f;
            br.z = (n0 + bn4 + 2 < N) ? Bp[n0 + bn4 + 2] : 0.f;
            br.w = (n0 + bn4 + 3 < N) ? Bp[n0 + bn4 + 3] : 0.f;
        }
    }
    {
        As[0][ak4 + 0][arow] = ar.x; As[0][ak4 + 1][arow] = ar.y;
        As[0][ak4 + 2][arow] = ar.z; As[0][ak4 + 3][arow] = ar.w;
        if (TRANSB) {
            Bs[0][ak4 + 0][arow] = br.x; Bs[0][ak4 + 1][arow] = br.y;
            Bs[0][ak4 + 2][arow] = br.z; Bs[0][ak4 + 3][arow] = br.w;
        } else {
            *(float4*)&Bs[0][bk][bn4] = br;
        }
    }
    __syncthreads();

    float acc[8][8] = {};
    for (int t = 0; t < nk; t++) {
        const int buf = t & 1;
        const int kn = (t + 1) << 3;
        if (t + 1 < nk) {
            ar = (m0 + arow < M) ? *(const float4*)(A + (long long)(m0 + arow) * lda + kn + ak4) : fz;
            if (TRANSB) {
                br = (n0 + arow < N) ? *(const float4*)(B + (long long)(n0 + arow) * ldb + kn + ak4) : fz;
            } else {
                if (n0 + bn4 + 3 < N) {
                    br = *(const float4*)(B + (long long)(kn + bk) * ldb + n0 + bn4);
                } else {
                    const float* Bp = B + (long long)(kn + bk) * ldb;
                    br.x = (n0 + bn4 + 0 < N) ? Bp[n0 + bn4 + 0] : 0.f;
                    br.y = (n0 + bn4 + 1 < N) ? Bp[n0 + bn4 + 1] : 0.f;
                    br.z = (n0 + bn4 + 2 < N) ? Bp[n0 + bn4 + 2] : 0.f;
                    br.w = (n0 + bn4 + 3 < N) ? Bp[n0 + bn4 + 3] : 0.f;
                }
            }
        }
#pragma unroll
        for (int k = 0; k < 8; k++) {
            float a[8], b[8];
            *(float4*)(a)     = *(const float4*)&As[buf][k][ty * 8];
            *(float4*)(a + 4) = *(const float4*)&As[buf][k][ty * 8 + 4];
            *(float4*)(b)     = *(const float4*)&Bs[buf][k][tx * 8];
            *(float4*)(b + 4) = *(const float4*)&Bs[buf][k][tx * 8 + 4];
#pragma unroll
            for (int i = 0; i < 8; i++)
#pragma unroll
                for (int j = 0; j < 8; j++) acc[i][j] += a[i] * b[j];
        }
        if (t + 1 < nk) {
            const int b2 = buf ^ 1;
            As[b2][ak4 + 0][arow] = ar.x; As[b2][ak4 + 1][arow] = ar.y;
            As[b2][ak4 + 2][arow] = ar.z; As[b2][ak4 + 3][arow] = ar.w;
            if (TRANSB) {
                Bs[b2][ak4 + 0][arow] = br.x; Bs[b2][ak4 + 1][arow] = br.y;
                Bs[b2][ak4 + 2][arow] = br.z; Bs[b2][ak4 + 3][arow] = br.w;
            } else {
                *(float4*)&Bs[b2][bk][bn4] = br;
            }
        }
        __syncthreads();
    }

#pragma unroll
    for (int i = 0; i < 8; i++) {
        int m = m0 + ty * 8 + i;
        if (m >= M) continue;
        float* Cr = Cp + (long long)m * ldc;
#pragma unroll
        for (int j = 0; j < 8; j++) {
            int n = n0 + tx * 8 + j;
            if (n < N) Cr[n] = alpha * acc[i][j];
        }
    }
}

template <bool TRANSB>
__global__ __launch_bounds__(256, 2)
void sgemm128_kernel(const float* __restrict__ A, long long sA, int lda,
                     const float* __restrict__ B, long long sB, int ldb,
                     float* __restrict__ Cp, long long sC, int ldc,
                     int M, int N, int K, float alpha) {
    sgemm128_core<TRANSB>(A + blockIdx.z * sA, lda, B + blockIdx.z * sB, ldb,
                          Cp + blockIdx.z * sC, ldc, M, N, K, alpha,
                          blockIdx.y * 128, blockIdx.x * 128);
}

// Fused T = W @ Linv^T and G = query @ Linv^T in one launch (shared B).
__global__ __launch_bounds__(256, 2)
void sgemm128_dual_kernel(const float* __restrict__ A1, int M1, int nby1,
                          const float* __restrict__ A2, int M2,
                          const float* __restrict__ B,
                          float* __restrict__ C1, float* __restrict__ C2) {
    if ((int)blockIdx.y < nby1) {
        sgemm128_core<true>(A1, Dd, B, Dd, C1, Dd, M1, Dd, Dd, 1.0f,
                            blockIdx.y * 128, blockIdx.x * 128);
    } else {
        sgemm128_core<true>(A2, Dd, B, Dd, C2, Dd, M2, Dd, Dd, 1.0f,
                            (blockIdx.y - nby1) * 128, blockIdx.x * 128);
    }
}

// ------------------------- per-class means (xbar, mu) ------------------------
__global__ void build_mu_kernel(const float* __restrict__ support,
                                const float* __restrict__ m) {
    int idx = blockIdx.x * blockDim.x + threadIdx.x;  // over C * D
    if (idx >= Cc * Dd) return;
    int c = idx / Dd, d = idx % Dd;
    float s = 0.f;
    for (int j = 0; j < SHOTSn; j++)
        s += support[(long long)g_sample_of[c * SHOTSn + j] * Dd + d];
    float xbar = s / g_cls[c].Nj;
    float mu = (g_kappa_ * m[d] + s) / g_cls[c].kN;
    g_xbar[idx] = xbar;
    g_mu[idx] = mu;
}

// ------------------------------- build W -------------------------------------
__global__ void build_W_kernel(const float* __restrict__ support,
                               const float* __restrict__ m) {
    int idx = blockIdx.x * blockDim.x + threadIdx.x;
    if (idx >= Cc * KW * Dd) return;
    int d = idx % Dd;
    int row = idx / Dd;
    int c = row / KW;
    int k = row % KW;
    float v;
    if (k < SHOTSn) {
        v = support[(long long)g_sample_of[c * SHOTSn + k] * Dd + d] - g_xbar[c * Dd + d];
    } else if (k == SHOTSn) {
        Cls cl = g_cls[c];
        float c2 = sqrtf(g_kappa_ * cl.Nj / cl.kN);
        v = c2 * (g_xbar[c * Dd + d] - m[d]);
    } else {
        v = g_mu[c * Dd + d];
    }
    g_W[idx] = v;
}

// ------------------------------- row norms -----------------------------------
__global__ void rownorm_kernel(const float* __restrict__ X, int ld, float* __restrict__ out) {
    int r = blockIdx.x, t = threadIdx.x;  // 256 threads
    const float* row = X + (long long)r * ld;
    float s = 0.f;
    for (int j = t; j < ld; j += blockDim.x) { float v = row[j]; s += v * v; }
    __shared__ float red[8];
    for (int o = 16; o > 0; o >>= 1) s += __shfl_down_sync(0xffffffffu, s, o);
    if ((t & 31) == 0) red[t >> 5] = s;
    __syncthreads();
    if (t < 32) {
        float v = (t < 8) ? red[t] : 0.f;
        for (int o = 4; o > 0; o >>= 1) v += __shfl_down_sync(0xffffffffu, v, o);
        if (t == 0) out[r] = v;
    }
}

// -------- per-class SPD 33x33 inverse (fp64 Gauss-Jordan) + logdet/bias ------
__global__ void small_inv_kernel() {
    int c = blockIdx.x, t = threadIdx.x;  // 64 threads
    __shared__ double Ms[KV][KV + 1];
    __shared__ double Iv[KV][KV + 1];
    __shared__ double s_logdet;
    __shared__ int    s_piv;
    const float* TtT = g_TtT + c * KW * KW;
    for (int i = t; i < KV * KV; i += blockDim.x) {
        int r = i / KV, cc = i % KV;
        Ms[r][cc] = (double)TtT[r * KW + cc] + (r == cc ? 1.0 : 0.0);  // M = I + T T^T
        Iv[r][cc] = (r == cc) ? 1.0 : 0.0;
    }
    if (t < KV) g_b[c * KW + t] = TtT[t * KW + (KW - 1)];  // t_a . t_mu
    if (t == 0) s_logdet = 0.0;
    __syncthreads();
    for (int k = 0; k < KV; k++) {
        if (t == 0) {
            int p = k; double best = fabs(Ms[k][k]);
            for (int r = k + 1; r < KV; r++) {
                double a = fabs(Ms[r][k]);
                if (a > best) { best = a; p = r; }
            }
            s_piv = p;
        }
        __syncthreads();
        int p = s_piv;
        if (p != k && t < KV) {
            double tmp = Ms[k][t]; Ms[k][t] = Ms[p][t]; Ms[p][t] = tmp;
            tmp = Iv[k][t]; Iv[k][t] = Iv[p][t]; Iv[p][t] = tmp;
        }
        __syncthreads();
        double piv = Ms[k][k];
        if (t == 0) s_logdet += log(fabs(piv));
        double pivinv = 1.0 / piv;
        if (t < KV) { Ms[k][t] *= pivinv; Iv[k][t] *= pivinv; }
        __syncthreads();
        if (t < KV && t != k) {
            double f = Ms[t][k];
            for (int j = 0; j < KV; j++) {
                Ms[t][j] -= f * Ms[k][j];
                Iv[t][j] -= f * Iv[k][j];
            }
        }
        __syncthreads();
    }
    for (int i = t; i < KV * KV; i += blockDim.x)
        g_Kinv[c * KW * KW + i] = (float)Iv[i / KV][i % KV];
    if (t == 0) {
        Cls cl = g_cls[c];
        double logdetS = 2.0 * (double)g_sumlogL + s_logdet;
        double logdet_sigma = (double)Dd * log((double)cl.scale) + logdetS;
        double common_ = (double)cl.common_;
        double bias = lgamma(0.5 * (common_ + (double)Dd)) - lgamma(0.5 * common_)
                    - 0.5 * (double)Dd * log(common_) - 0.5 * logdet_sigma;
        g_cls[c].bias = (float)bias;
        g_cls[c].hh = TtT[(KW - 1) * KW + (KW - 1)];  // ||t_mu||^2
    }
}

// --------------------------------- finalize ----------------------------------
__global__ void finalize_kernel(float* __restrict__ out) {
    int c = blockIdx.y;
    int q = blockIdx.x * blockDim.x + threadIdx.x;
    __shared__ float Ks[KV * KV];
    __shared__ float bs[KV];
    __shared__ Cls cl;
    for (int i = threadIdx.x; i < KV * KV; i += blockDim.x) Ks[i] = g_Kinv[c * KW * KW + i];
    if (threadIdx.x < KV) bs[threadIdx.x] = g_b[c * KW + threadIdx.x];
    if (threadIdx.x == 0) cl = g_cls[c];
    __syncthreads();
    if (q >= Qq) return;
    const float* Ur = g_U + (long long)q * NU + c * KW;
    float v[KV];
    float u33 = Ur[KW - 1];  // g . t_mu
#pragma unroll
    for (int i = 0; i < KV; i++) v[i] = Ur[i] - bs[i];  // u_a = t_a.(g - t_mu)
    float s = 0.f;
#pragma unroll 4
    for (int i = 0; i < KV; i++) {
        float acc = 0.f;
#pragma unroll
        for (int j = 0; j < KV; j++) acc += Ks[i * KV + j] * v[j];
        s += v[i] * acc;
    }
    float distA = g_Gn2[q] - 2.0f * u33 + cl.hh - s;
    float dist  = cl.invscale_half * distA
                + 0.5f * (g_qn2[q] - 2.0f * g_qm[q * Cc + c] + g_mun2[c]);
    out[(long long)q * Cc + c] = cl.bias - cl.coefD * log1pf(dist * cl.inv_common);
}

// ------------------------------ host launchers -------------------------------
static void sgemm_small(const float* A, long long sA, int lda,
                        const float* B, long long sB, int ldb,
                        float* Cmat, long long sC, int ldc,
                        int M, int N, int K, float alpha, bool transB, int batch) {
    dim3 grid((N + 63) / 64, (M + 63) / 64, batch);
    if (transB)
        sgemm_kernel<true><<<grid, 256>>>(A, sA, lda, B, sB, ldb, Cmat, sC, ldc, M, N, K, alpha);
    else
        sgemm_kernel<false><<<grid, 256>>>(A, sA, lda, B, sB, ldb, Cmat, sC, ldc, M, N, K, alpha);
}

static void sgemm_big(const float* A, long long sA, int lda,
                      const float* B, long long sB, int ldb,
                      float* Cmat, long long sC, int ldc,
                      int M, int N, int K, float alpha, bool transB, int batch) {
    dim3 grid((N + 127) / 128, (M + 127) / 128, batch);
    if (transB)
        sgemm128_kernel<true><<<grid, 256>>>(A, sA, lda, B, sB, ldb, Cmat, sC, ldc, M, N, K, alpha);
    else
        sgemm128_kernel<false><<<grid, 256>>>(A, sA, lda, B, sB, ldb, Cmat, sC, ldc, M, N, K, alpha);
}

extern "C" void kernel_launch(void* const* d_in, const int* in_sizes, int n_in,
                              void* d_out, int out_size) {
    const float* support = (const float*)d_in[0];
    const float* query   = (const float*)d_in[1];
    const int*   labels  = (const int*)d_in[2];
    const float* m       = (const float*)d_in[3];
    const float* kappa   = (const float*)d_in[4];
    const float* nu      = (const float*)d_in[5];
    const float* tdiag   = (const float*)d_in[6];
    const float* tlower  = (const float*)d_in[7];
    float* out = (float*)d_out;

    float *pL, *pLinv, *pTmp, *pW, *pT, *pG, *pU, *pTtT, *pMu, *pGn2, *pqn2, *pmun2, *pQm;
    cudaGetSymbolAddress((void**)&pL, g_L);
    cudaGetSymbolAddress((void**)&pLinv, g_Linv);
    cudaGetSymbolAddress((void**)&pTmp, g_Tmp);
    cudaGetSymbolAddress((void**)&pW, g_W);
    cudaGetSymbolAddress((void**)&pT, g_T);
    cudaGetSymbolAddress((void**)&pG, g_G);
    cudaGetSymbolAddress((void**)&pU, g_U);
    cudaGetSymbolAddress((void**)&pTtT, g_TtT);
    cudaGetSymbolAddress((void**)&pMu, g_mu);
    cudaGetSymbolAddress((void**)&pGn2, g_Gn2);
    cudaGetSymbolAddress((void**)&pqn2, g_qn2);
    cudaGetSymbolAddress((void**)&pmun2, g_mun2);
    cudaGetSymbolAddress((void**)&pQm, g_qm);

    // 1) scalars, per-class params, stable sample gather, sum log|diag L|
    setup_kernel<<<1, NSUP>>>(labels, kappa, nu, tdiag);

    // 2) per-class xbar / mu, then W = [X_c - xbar | sqrt(.)*(xbar-m) | mu_c]
    build_mu_kernel<<<(Cc * Dd + 255) / 256, 256>>>(support, m);
    build_W_kernel<<<(Cc * KW * Dd + 255) / 256, 256>>>(support, m);

    // 3) L and L^{-1} (recursive-doubling blocked triangular inverse)
    build_L_kernel<<<(Dd * Dd + 255) / 256, 256>>>(tdiag, tlower);
    inv_diag_kernel<<<32, 32>>>();
    for (int lev = 1; lev <= 5; lev++) {
        int s = 32 << (lev - 1);
        int pairs = 32 >> lev;
        long long stride = 2LL * s * (Dd + 1);
        if (s < 128) {
            sgemm_small(pL + (long long)s * Dd, stride, Dd,
                        pLinv, stride, Dd,
                        pTmp, (long long)s * s, s,
                        s, s, s, 1.0f, false, pairs);
            sgemm_small(pLinv + (long long)s * Dd + s, stride, Dd,
                        pTmp, (long long)s * s, s,
                        pLinv + (long long)s * Dd, stride, Dd,
                        s, s, s, -1.0f, false, pairs);
        } else {
            sgemm_big(pL + (long long)s * Dd, stride, Dd,
                      pLinv, stride, Dd,
                      pTmp, (long long)s * s, s,
                      s, s, s, 1.0f, false, pairs);
            sgemm_big(pLinv + (long long)s * Dd + s, stride, Dd,
                      pTmp, (long long)s * s, s,
                      pLinv + (long long)s * Dd, stride, Dd,
                      s, s, s, -1.0f, false, pairs);
        }
    }

    // 4+5) fused: T = W @ Linv^T [1088x1024] and G = query @ Linv^T [1024x1024]
    {
        int nby1 = (NU + 127) / 128;       // 9
        int nby2 = (Qq + 127) / 128;       // 8
        dim3 grid(Dd / 128, nby1 + nby2);  // (8, 17)
        sgemm128_dual_kernel<<<grid, 256>>>(pW, NU, nby1, query, Qq, pLinv, pT, pG);
    }

    // 6) row norms: ||L^{-1}q||^2, ||q||^2, ||mu||^2
    rownorm_kernel<<<Qq, 256>>>(pG, Dd, pGn2);
    rownorm_kernel<<<Qq, 256>>>(query, Dd, pqn2);
    rownorm_kernel<<<Cc, 256>>>(pMu, Dd, pmun2);

    // 7) T^T T per class [34x34]; M = I + [0:33,0:33] inverted in fp64 + logdet/bias
    sgemm_small(pT, (long long)KW * Dd, Dd, pT, (long long)KW * Dd, Dd,
                pTtT, (long long)KW * KW, KW, KW, KW, Dd, 1.0f, true, Cc);
    small_inv_kernel<<<Cc, 64>>>();

    // 8) U = G @ T^T  [1024 x 1088]  (dense, no batch waste)
    sgemm_big(pG, 0, Dd, pT, 0, Dd, pU, 0, NU, Qq, NU, Dd, 1.0f, true, 1);

    // 9) qm = query @ mu^T  [Q x C]   (ldb fixed to Dd)
    sgemm_small(query, 0, Dd, pMu, 0, Dd, pQm, 0, Cc, Qq, Cc, Dd, 1.0f, true, 1);

    // 10) fuse quadratic forms + bias + log1p
    finalize_kernel<<<dim3((Qq + 127) / 128, Cc), 128>>>(out);
}